// round 7
// baseline (speedup 1.0000x reference)
#include <cuda_runtime.h>
#include <cuda_bf16.h>
#include <math.h>

#define B_     2
#define S_     32
#define BS_    64
#define C_     128
#define HGT    24
#define WID    24
#define L_     576
#define HEADS_ 2
#define QKD_   64
#define VD_    128
#define HID_   256
#define OUTC_  128

// ---------------- scratch (static device globals; no allocation) ----------------
__device__ float g_bias[HEADS_ * L_ * L_];            // (head, i, j)  fp32, true order
__device__ float g_q[BS_ * HEADS_ * L_ * QKD_];       // [bs,h][l][d-interleaved], tf32
__device__ float g_k[BS_ * HEADS_ * L_ * QKD_];       // [bs,h][l][d-interleaved], tf32
__device__ float g_v[BS_ * HEADS_ * VD_ * L_];        // [bs,h][d][l-interleaved], tf32
__device__ float g_att[BS_ * L_ * HID_];              // [bs][l][ch-interleaved], tf32
// pre-permuted + tf32-rounded weights (k-dim interleaved within 8-blocks)
__device__ float g_wqk[2 * C_ * C_];                  // 256 x 128
__device__ float g_wv [HID_ * C_];                    // 256 x 128
__device__ float g_w1p[HID_ * HID_];                  // 256 x 256
__device__ float g_w2p[OUTC_ * HID_];                 // 128 x 256

// ---------------- helpers ----------------
__device__ __forceinline__ int perm8(int i) {
    return (i & ~7) | (((i & 3) << 1) | ((i >> 2) & 1));
}
__device__ __forceinline__ unsigned f2tf(float f) {
    unsigned r;
    asm("cvt.rna.tf32.f32 %0, %1;" : "=r"(r) : "f"(f));
    return r;
}
__device__ __forceinline__ float tfr(float f) { return __uint_as_float(f2tf(f)); }
__device__ __forceinline__ void mma_tf32(float c[4],
                                         float a0, float a1, float a2, float a3,
                                         float b0, float b1) {
    asm volatile(
        "mma.sync.aligned.m16n8k8.row.col.f32.tf32.tf32.f32 "
        "{%0,%1,%2,%3}, {%4,%5,%6,%7}, {%8,%9}, {%0,%1,%2,%3};"
        : "+f"(c[0]), "+f"(c[1]), "+f"(c[2]), "+f"(c[3])
        : "r"(__float_as_uint(a0)), "r"(__float_as_uint(a1)),
          "r"(__float_as_uint(a2)), "r"(__float_as_uint(a3)),
          "r"(__float_as_uint(b0)), "r"(__float_as_uint(b1)));
}

// ---------------- kernel 0: weight prep (permute k within 8-blocks + tf32 round) ----------------
__global__ void prep_kernel(const float* __restrict__ qk_w, const float* __restrict__ v_w,
                            const float* __restrict__ w1, const float* __restrict__ w2) {
    int idx = blockIdx.x * 256 + threadIdx.x;     // 0 .. 163839
    if (idx < 32768) {
        int o = idx >> 7, k = idx & 127;
        g_wqk[(o << 7) | perm8(k)] = tfr(qk_w[idx]);
    } else if (idx < 65536) {
        int j = idx - 32768; int o = j >> 7, k = j & 127;
        g_wv[(o << 7) | perm8(k)] = tfr(v_w[j]);
    } else if (idx < 131072) {
        int j = idx - 65536; int o = j >> 8, k = j & 255;
        g_w1p[(o << 8) | perm8(k)] = tfr(w1[j]);
    } else {
        int j = idx - 131072; int o = j >> 8, k = j & 255;
        g_w2p[(o << 8) | perm8(k)] = tfr(w2[j]);
    }
}

// ---------------- kernel 1: continuous relative position bias ----------------
__global__ void cpb_bias_kernel(const float* __restrict__ w1,
                                const float* __restrict__ b1,
                                const float* __restrict__ w2) {
    __shared__ float s_w1[256];
    __shared__ float s_b1[128];
    __shared__ float s_w2[256];
    int tid = threadIdx.x;
    s_w1[tid] = w1[tid];
    if (tid < 128) s_b1[tid] = b1[tid];
    s_w2[tid] = w2[tid];
    __syncthreads();

    int idx = blockIdx.x * 256 + tid;      // < 576*576
    int i = idx / L_, j = idx % L_;
    int yi = i / WID, xi = i % WID;
    int yj = j / WID, xj = j % WID;
    float ry = (float)(yi - yj) * (8.0f / 23.0f);
    float rx = (float)(xi - xj) * (8.0f / 23.0f);
    ry = copysignf(log2f(1.0f + fabsf(ry)) * (1.0f / 3.0f), ry);
    rx = copysignf(log2f(1.0f + fabsf(rx)) * (1.0f / 3.0f), rx);

    float acc0 = 0.f, acc1 = 0.f;
    #pragma unroll 4
    for (int k = 0; k < 128; k++) {
        float h = fmaxf(0.f, ry * s_w1[2 * k] + rx * s_w1[2 * k + 1] + s_b1[k]);
        acc0 += h * s_w2[k];
        acc1 += h * s_w2[128 + k];
    }
    g_bias[idx] = acc0;
    g_bias[L_ * L_ + idx] = acc1;
}

// ---------------- kernel 2: QKV projection, tf32 mma ----------------
// Block: (l-tile 64, bs). 256 threads = 8 warps.
__global__ void qkv_kernel(const float* __restrict__ x) {
    int bs = blockIdx.y;
    int l0 = blockIdx.x * 64;
    extern __shared__ float sm[];
    float* xs   = sm;                   // 128*72
    float* ws   = xs + 128 * 72;        // 64*136
    float* outs = ws + 64 * 136;        // 64*72

    int tid = threadIdx.x;
    const float* xb = x + (size_t)bs * C_ * L_;
    for (int idx = tid; idx < 128 * 16; idx += 256) {
        int c = idx >> 4, lv = idx & 15;
        float4 v4 = *(const float4*)(xb + (size_t)c * L_ + l0 + lv * 4);
        v4.x = tfr(v4.x); v4.y = tfr(v4.y); v4.z = tfr(v4.z); v4.w = tfr(v4.w);
        *(float4*)(xs + c * 72 + lv * 4) = v4;
    }

    int warp = tid >> 5, lane = tid & 31;
    int row = lane >> 2, quad = lane & 3;
    int m0 = (warp & 3) * 16;           // o within chunk
    int n0 = (warp >> 2) * 32;          // l within tile

    for (int ot = 0; ot < 8; ot++) {
        const float* wsrc = (ot < 4) ? g_wqk + (size_t)ot * 64 * C_
                                     : g_wv  + (size_t)(ot - 4) * 64 * C_;
        __syncthreads();
        for (int idx = tid; idx < 64 * 32; idx += 256) {
            int o = idx >> 5, kv = idx & 31;
            *(float4*)(ws + o * 136 + kv * 4) = *(const float4*)(wsrc + (size_t)o * C_ + kv * 4);
        }
        __syncthreads();

        float acc[4][4] = {};
        #pragma unroll
        for (int kk = 0; kk < 16; kk++) {
            int k0 = kk * 8;
            float2 aA = *(float2*)(ws + (m0 + row) * 136 + k0 + 2 * quad);      // a0,a2
            float2 aB = *(float2*)(ws + (m0 + row + 8) * 136 + k0 + 2 * quad);  // a1,a3
            #pragma unroll
            for (int nt = 0; nt < 4; nt++) {
                int n = n0 + nt * 8;
                float b0 = xs[(k0 + quad) * 72 + n + row];
                float b1 = xs[(k0 + quad + 4) * 72 + n + row];
                mma_tf32(acc[nt], aA.x, aB.x, aA.y, aB.y, b0, b1);
            }
        }

        if (ot < 4) {
            // Q/K: outs[l][perm(d)]
            int po0 = perm8(m0 + row), po1 = perm8(m0 + row + 8);
            #pragma unroll
            for (int nt = 0; nt < 4; nt++) {
                int n = n0 + nt * 8 + 2 * quad;
                outs[n * 72 + po0]       = tfr(acc[nt][0]);
                outs[(n + 1) * 72 + po0] = tfr(acc[nt][1]);
                outs[n * 72 + po1]       = tfr(acc[nt][2]);
                outs[(n + 1) * 72 + po1] = tfr(acc[nt][3]);
            }
            __syncthreads();
            float* dst = (ot < 2) ? g_q + (size_t)(bs * 2 + ot) * L_ * QKD_
                                  : g_k + (size_t)(bs * 2 + ot - 2) * L_ * QKD_;
            for (int idx = tid; idx < 64 * 16; idx += 256) {
                int l = idx >> 4, j = idx & 15;
                *(float4*)(dst + (size_t)(l0 + l) * QKD_ + j * 4) =
                    *(float4*)(outs + l * 72 + j * 4);
            }
        } else {
            // V: outs[d][perm(l)]  (transposed, l-interleaved)
            #pragma unroll
            for (int nt = 0; nt < 4; nt++) {
                int cl = n0 + nt * 8 + 2 * quad;
                int p0 = perm8(cl), p1 = perm8(cl + 1);
                outs[(m0 + row) * 72 + p0]     = tfr(acc[nt][0]);
                outs[(m0 + row) * 72 + p1]     = tfr(acc[nt][1]);
                outs[(m0 + row + 8) * 72 + p0] = tfr(acc[nt][2]);
                outs[(m0 + row + 8) * 72 + p1] = tfr(acc[nt][3]);
            }
            __syncthreads();
            int o2 = (ot - 4) * 64;
            int head = o2 >> 7, dof = o2 & 127;
            float* dst = g_v + (size_t)(bs * 2 + head) * VD_ * L_;
            for (int idx = tid; idx < 64 * 16; idx += 256) {
                int o = idx >> 4, j = idx & 15;
                *(float4*)(dst + (size_t)(dof + o) * L_ + l0 + j * 4) =
                    *(float4*)(outs + o * 72 + j * 4);
            }
        }
    }
}

// ---------------- kernel 3: flash attention, q-tile 128, 512 threads, 1 CTA/SM ----------------
// smem: qs[128][72], ks[64][72], vt[128][72], ps[128][72], mrow/lrow/arow[128]
__global__ void __launch_bounds__(512, 1) attn_kernel(const float* __restrict__ sa_bias) {
    int qt = blockIdx.x;              // 0..4 (last tile half)
    int bh = blockIdx.y;              // 0..127
    int bs = bh >> 1, head = bh & 1;
    int q0 = qt * 128;

    extern __shared__ float sm[];
    float* qs   = sm;                  // 128*72
    float* ks   = qs + 128 * 72;       // 64*72
    float* vt   = ks + 64 * 72;        // 128*72
    float* ps   = vt + 128 * 72;       // 128*72
    float* mrow = ps + 128 * 72;       // 128
    float* lrow = mrow + 128;          // 128
    float* arow = lrow + 128;          // 128

    const float* qg = g_q + (size_t)(bs * 2 + head) * L_ * QKD_;
    const float* kg = g_k + (size_t)(bs * 2 + head) * L_ * QKD_;
    const float* vg = g_v + (size_t)(bs * 2 + head) * VD_ * L_;
    const float* bg = g_bias + (size_t)head * L_ * L_;

    int tid = threadIdx.x;
    int warp = tid >> 5, lane = tid & 31;
    int row = lane >> 2, quad = lane & 3;
    int m0  = (warp & 3) * 32;         // q rows (warp m-tile 32)
    int n0s = (warp >> 2) * 16;        // score n-tile
    int n0v = (warp >> 2) * 32;        // AV n-tile

    // load q tile [128][64], zero-fill rows >= 576
    for (int idx = tid; idx < 128 * 16; idx += 512) {
        int l = idx >> 4, dv = idx & 15;
        float4 v4 = make_float4(0.f, 0.f, 0.f, 0.f);
        if (q0 + l < L_)
            v4 = *(const float4*)(qg + (size_t)(q0 + l) * QKD_ + dv * 4);
        *(float4*)(qs + l * 72 + dv * 4) = v4;
    }
    if (tid < 128) { mrow[tid] = -1e30f; lrow[tid] = 0.f; }

    float oac[2][4][4] = {};

    for (int kt = 0; kt < 9; kt++) {
        __syncthreads();
        // stage K tile [64 keys][64 d]
        for (int idx = tid; idx < 64 * 16; idx += 512) {
            int l = idx >> 4, dv = idx & 15;
            *(float4*)(ks + l * 72 + dv * 4) =
                *(const float4*)(kg + (size_t)(kt * 64 + l) * QKD_ + dv * 4);
        }
        // stage V tile [128 d][64 keys-interleaved]
        for (int idx = tid; idx < 128 * 16; idx += 512) {
            int d = idx >> 4, j = idx & 15;
            *(float4*)(vt + d * 72 + j * 4) =
                *(const float4*)(vg + (size_t)d * L_ + kt * 64 + j * 4);
        }
        __syncthreads();

        // ---- S = Q K^T (warp m32 x n16) + bias, into ps (perm cols) ----
        float acc[2][2][4] = {};
        #pragma unroll
        for (int kk = 0; kk < 8; kk++) {
            int k0 = kk * 8;
            float2 aA[2], aB[2];
            #pragma unroll
            for (int mt = 0; mt < 2; mt++) {
                aA[mt] = *(float2*)(qs + (m0 + mt * 16 + row) * 72 + k0 + 2 * quad);
                aB[mt] = *(float2*)(qs + (m0 + mt * 16 + row + 8) * 72 + k0 + 2 * quad);
            }
            #pragma unroll
            for (int nt = 0; nt < 2; nt++) {
                float2 bv = *(float2*)(ks + (n0s + nt * 8 + row) * 72 + k0 + 2 * quad);
                mma_tf32(acc[0][nt], aA[0].x, aB[0].x, aA[0].y, aB[0].y, bv.x, bv.y);
                mma_tf32(acc[1][nt], aA[1].x, aB[1].x, aA[1].y, aB[1].y, bv.x, bv.y);
            }
        }
        #pragma unroll
        for (int mt = 0; mt < 2; mt++) {
            int rloc = m0 + mt * 16 + row;
            int r0 = q0 + rloc;
            int rb0 = (r0 < L_) ? r0 : L_ - 1;          // clamp for bias read (masked rows)
            int rb1 = (r0 + 8 < L_) ? r0 + 8 : L_ - 1;
            #pragma unroll
            for (int nt = 0; nt < 2; nt++) {
                int cl = n0s + nt * 8 + 2 * quad;
                int p0 = perm8(cl), p1 = perm8(cl + 1);
                int ct = kt * 64 + cl;
                ps[rloc * 72 + p0]       = acc[mt][nt][0] * 0.125f + bg[(size_t)rb0 * L_ + ct];
                ps[rloc * 72 + p1]       = acc[mt][nt][1] * 0.125f + bg[(size_t)rb0 * L_ + ct + 1];
                ps[(rloc + 8) * 72 + p0] = acc[mt][nt][2] * 0.125f + bg[(size_t)rb1 * L_ + ct];
                ps[(rloc + 8) * 72 + p1] = acc[mt][nt][3] * 0.125f + bg[(size_t)rb1 * L_ + ct + 1];
            }
        }
        __syncthreads();

        // ---- online softmax: warp owns rows warp*8 .. warp*8+7 ----
        #pragma unroll
        for (int rr = 0; rr < 8; rr++) {
            int r = warp * 8 + rr;
            float2 pv = *(float2*)(ps + r * 72 + 2 * lane);
            float tmax = fmaxf(pv.x, pv.y);
            #pragma unroll
            for (int off = 16; off > 0; off >>= 1)
                tmax = fmaxf(tmax, __shfl_xor_sync(0xffffffffu, tmax, off));
            float mo = mrow[r];
            float mn = fmaxf(mo, tmax);
            float e0 = __expf(pv.x - mn);
            float e1 = __expf(pv.y - mn);
            float2 pr; pr.x = tfr(e0); pr.y = tfr(e1);
            *(float2*)(ps + r * 72 + 2 * lane) = pr;
            float ss = e0 + e1;
            #pragma unroll
            for (int off = 16; off > 0; off >>= 1)
                ss += __shfl_xor_sync(0xffffffffu, ss, off);
            if (lane == 0) {
                float al = __expf(mo - mn);
                arow[r] = al;
                mrow[r] = mn;
                lrow[r] = al * lrow[r] + ss;
            }
        }
        __syncthreads();

        // ---- AV: warp m32 x n32, rescale + accumulate ----
        float al0 = arow[m0 + row],      al1 = arow[m0 + row + 8];
        float al2 = arow[m0 + 16 + row], al3 = arow[m0 + 24 + row];
        #pragma unroll
        for (int nt = 0; nt < 4; nt++) {
            oac[0][nt][0] *= al0; oac[0][nt][1] *= al0;
            oac[0][nt][2] *= al1; oac[0][nt][3] *= al1;
            oac[1][nt][0] *= al2; oac[1][nt][1] *= al2;
            oac[1][nt][2] *= al3; oac[1][nt][3] *= al3;
        }
        #pragma unroll
        for (int kk = 0; kk < 8; kk++) {
            int kb = kk * 8;
            float2 aA[2], aB[2];
            #pragma unroll
            for (int mt = 0; mt < 2; mt++) {
                aA[mt] = *(float2*)(ps + (m0 + mt * 16 + row) * 72 + kb + 2 * quad);
                aB[mt] = *(float2*)(ps + (m0 + mt * 16 + row + 8) * 72 + kb + 2 * quad);
            }
            #pragma unroll
            for (int nt = 0; nt < 4; nt++) {
                float2 bv = *(float2*)(vt + (n0v + nt * 8 + row) * 72 + kb + 2 * quad);
                mma_tf32(oac[0][nt], aA[0].x, aB[0].x, aA[0].y, aB[0].y, bv.x, bv.y);
                mma_tf32(oac[1][nt], aA[1].x, aB[1].x, aA[1].y, aB[1].y, bv.x, bv.y);
            }
        }
    }

    // ---- epilogue: normalize, + sa_bias, ch-interleaved tf32 write (masked) ----
    float* og = g_att + (size_t)bs * L_ * HID_;
    #pragma unroll
    for (int mt = 0; mt < 2; mt++) {
        int l0r = q0 + m0 + mt * 16 + row;
        float inv0 = 1.0f / lrow[m0 + mt * 16 + row];
        float inv1 = 1.0f / lrow[m0 + mt * 16 + row + 8];
        #pragma unroll
        for (int nt = 0; nt < 4; nt++) {
            int ch = head * 128 + n0v + nt * 8 + 2 * quad;
            int pc0 = perm8(ch), pc1 = perm8(ch + 1);
            float sb0 = sa_bias[ch], sb1 = sa_bias[ch + 1];
            if (l0r < L_) {
                og[(size_t)l0r * HID_ + pc0] = tfr(oac[mt][nt][0] * inv0 + sb0);
                og[(size_t)l0r * HID_ + pc1] = tfr(oac[mt][nt][1] * inv0 + sb1);
            }
            if (l0r + 8 < L_) {
                og[(size_t)(l0r + 8) * HID_ + pc0] = tfr(oac[mt][nt][2] * inv1 + sb0);
                og[(size_t)(l0r + 8) * HID_ + pc1] = tfr(oac[mt][nt][3] * inv1 + sb1);
            }
        }
    }
}

// ---------------- kernel 4: MLP (tf32 mma), 512 threads = 16 warps ----------------
// smem: xsm[64][264], wts[256][72], y1s[64][264]
__global__ void mlp_kernel(const float* __restrict__ b1, const float* __restrict__ b2,
                           float* __restrict__ out) {
    int blk = blockIdx.x;                // 0..575
    int bs = blk / 9;
    int l0 = (blk % 9) * 64;
    extern __shared__ float sm[];
    float* xsm = sm;                     // 64*264
    float* wts = xsm + 64 * 264;         // 256*72
    float* y1s = wts + 256 * 72;         // 64*264

    int tid = threadIdx.x;
    int warp = tid >> 5, lane = tid & 31;
    int row = lane >> 2, quad = lane & 3;

    const float* ag = g_att + ((size_t)bs * L_ + l0) * HID_;
    for (int idx = tid; idx < 64 * 64; idx += 512) {
        int p = idx >> 6, iv = idx & 63;
        *(float4*)(xsm + p * 264 + iv * 4) = *(const float4*)(ag + (size_t)p * HID_ + iv * 4);
    }

    // ---- GEMM1: Y1(64x256) = X @ W1^T : warp tile m32 x n32 ----
    int m0 = (warp & 1) * 32;
    int n0 = (warp >> 1) * 32;
    float acc[2][4][4] = {};
    for (int it = 0; it < 4; it++) {
        __syncthreads();
        for (int idx = tid; idx < 256 * 16; idx += 512) {
            int o = idx >> 4, kv = idx & 15;
            *(float4*)(wts + o * 72 + kv * 4) = *(const float4*)(g_w1p + (size_t)o * HID_ + it * 64 + kv * 4);
        }
        __syncthreads();
        #pragma unroll
        for (int kk = 0; kk < 8; kk++) {
            int kg = it * 64 + kk * 8;
            int kb = kk * 8;
            float2 aA[2], aB[2];
            #pragma unroll
            for (int mt = 0; mt < 2; mt++) {
                aA[mt] = *(float2*)(xsm + (m0 + mt * 16 + row) * 264 + kg + 2 * quad);
                aB[mt] = *(float2*)(xsm + (m0 + mt * 16 + row + 8) * 264 + kg + 2 * quad);
            }
            #pragma unroll
            for (int nt = 0; nt < 4; nt++) {
                float2 bv = *(float2*)(wts + (n0 + nt * 8 + row) * 72 + kb + 2 * quad);
                mma_tf32(acc[0][nt], aA[0].x, aB[0].x, aA[0].y, aB[0].y, bv.x, bv.y);
                mma_tf32(acc[1][nt], aA[1].x, aB[1].x, aA[1].y, aB[1].y, bv.x, bv.y);
            }
        }
    }
    // bias + exact GELU -> y1s[p][perm(o)], tf32-rounded
    #pragma unroll
    for (int mt = 0; mt < 2; mt++) {
        #pragma unroll
        for (int nt = 0; nt < 4; nt++) {
            int col = n0 + nt * 8 + 2 * quad;
            int p0 = perm8(col), p1 = perm8(col + 1);
            float bb0 = b1[col], bb1 = b1[col + 1];
            int r = m0 + mt * 16 + row;
            float v0 = acc[mt][nt][0] + bb0;
            float v1 = acc[mt][nt][1] + bb1;
            float v2 = acc[mt][nt][2] + bb0;
            float v3 = acc[mt][nt][3] + bb1;
            y1s[r * 264 + p0]       = tfr(0.5f * v0 * (1.0f + erff(v0 * 0.70710678118654752f)));
            y1s[r * 264 + p1]       = tfr(0.5f * v1 * (1.0f + erff(v1 * 0.70710678118654752f)));
            y1s[(r + 8) * 264 + p0] = tfr(0.5f * v2 * (1.0f + erff(v2 * 0.70710678118654752f)));
            y1s[(r + 8) * 264 + p1] = tfr(0.5f * v3 * (1.0f + erff(v3 * 0.70710678118654752f)));
        }
    }
    __syncthreads();

    // ---- GEMM2: OUT(64x128) = Y1 @ W2^T : warp tile m16 x n32 ----
    int m0b = (warp & 3) * 16;
    int n0b = (warp >> 2) * 32;
    float ac2[4][4] = {};
    for (int it = 0; it < 4; it++) {
        for (int idx = tid; idx < 128 * 16; idx += 512) {
            int o = idx >> 4, kv = idx & 15;
            *(float4*)(wts + o * 72 + kv * 4) = *(const float4*)(g_w2p + (size_t)o * HID_ + it * 64 + kv * 4);
        }
        __syncthreads();
        #pragma unroll
        for (int kk = 0; kk < 8; kk++) {
            int kg = it * 64 + kk * 8;
            int kb = kk * 8;
            float2 aA = *(float2*)(y1s + (m0b + row) * 264 + kg + 2 * quad);
            float2 aB = *(float2*)(y1s + (m0b + row + 8) * 264 + kg + 2 * quad);
            #pragma unroll
            for (int nt = 0; nt < 4; nt++) {
                float2 bv = *(float2*)(wts + (n0b + nt * 8 + row) * 72 + kb + 2 * quad);
                mma_tf32(ac2[nt], aA.x, aB.x, aA.y, aB.y, bv.x, bv.y);
            }
        }
        __syncthreads();
    }

    // ---- epilogue: + b2, write (bs, o, l) ----
    float* og = out + (size_t)bs * OUTC_ * L_;
    int l = l0 + m0b + row;
    #pragma unroll
    for (int nt = 0; nt < 4; nt++) {
        int col = n0b + nt * 8 + 2 * quad;
        float bb0 = b2[col], bb1 = b2[col + 1];
        og[(size_t)col * L_ + l]           = ac2[nt][0] + bb0;
        og[(size_t)(col + 1) * L_ + l]     = ac2[nt][1] + bb1;
        og[(size_t)col * L_ + l + 8]       = ac2[nt][2] + bb0;
        og[(size_t)(col + 1) * L_ + l + 8] = ac2[nt][3] + bb1;
    }
}

// ---------------- launch ----------------
extern "C" void kernel_launch(void* const* d_in, const int* in_sizes, int n_in,
                              void* d_out, int out_size) {
    const float* x      = (const float*)d_in[0];
    const float* qk_w   = (const float*)d_in[1];
    const float* v_w    = (const float*)d_in[2];
    const float* cpb_w1 = (const float*)d_in[3];
    const float* cpb_b1 = (const float*)d_in[4];
    const float* cpb_w2 = (const float*)d_in[5];
    const float* sa_b   = (const float*)d_in[6];
    const float* mlp_b1 = (const float*)d_in[8];
    const float* mlp_b2 = (const float*)d_in[10];
    float* out = (float*)d_out;

    const int SMEM_QKV = (128 * 72 + 64 * 136 + 64 * 72) * 4;                  // 90112
    const int SMEM_ATT = ((128 + 64 + 128 + 128) * 72 + 3 * 128) * 4;          // 130560
    const int SMEM_MLP = (64 * 264 * 2 + 256 * 72) * 4;                        // 208896

    cudaFuncSetAttribute(qkv_kernel,  cudaFuncAttributeMaxDynamicSharedMemorySize, SMEM_QKV);
    cudaFuncSetAttribute(attn_kernel, cudaFuncAttributeMaxDynamicSharedMemorySize, SMEM_ATT);
    cudaFuncSetAttribute(mlp_kernel,  cudaFuncAttributeMaxDynamicSharedMemorySize, SMEM_MLP);

    prep_kernel<<<640, 256>>>(qk_w, v_w, (const float*)d_in[7], (const float*)d_in[9]);
    cpb_bias_kernel<<<(L_ * L_) / 256, 256>>>(cpb_w1, cpb_b1, cpb_w2);
    qkv_kernel<<<dim3(9, BS_), 256, SMEM_QKV>>>(x);
    attn_kernel<<<dim3(5, BS_ * HEADS_), 512, SMEM_ATT>>>(sa_b);
    mlp_kernel<<<BS_ * 9, 512, SMEM_MLP>>>(mlp_b1, mlp_b2, out);
}

// round 8
// speedup vs baseline: 1.1772x; 1.1772x over previous
#include <cuda_runtime.h>
#include <cuda_bf16.h>
#include <math.h>

#define B_     2
#define S_     32
#define BS_    64
#define C_     128
#define HGT    24
#define WID    24
#define L_     576
#define HEADS_ 2
#define QKD_   64
#define VD_    128
#define HID_   256
#define OUTC_  128

// ---------------- scratch (static device globals; no allocation) ----------------
__device__ float g_bias[HEADS_ * L_ * L_];            // (head, i, j)  fp32, true order
__device__ float g_q[BS_ * HEADS_ * L_ * QKD_];       // [bs,h][l][d-interleaved], tf32
__device__ float g_k[BS_ * HEADS_ * L_ * QKD_];       // [bs,h][l][d-interleaved], tf32
__device__ float g_v[BS_ * HEADS_ * VD_ * L_];        // [bs,h][d][l-interleaved], tf32
__device__ float g_att[BS_ * L_ * HID_];              // [bs][l][ch-interleaved], tf32
// pre-permuted + tf32-rounded weights (k-dim interleaved within 8-blocks)
__device__ float g_wqk[2 * C_ * C_];                  // 256 x 128
__device__ float g_wv [HID_ * C_];                    // 256 x 128
__device__ float g_w1p[HID_ * HID_];                  // 256 x 256
__device__ float g_w2p[OUTC_ * HID_];                 // 128 x 256

// ---------------- helpers ----------------
__device__ __forceinline__ int perm8(int i) {
    return (i & ~7) | (((i & 3) << 1) | ((i >> 2) & 1));
}
__device__ __forceinline__ unsigned f2tf(float f) {
    unsigned r;
    asm("cvt.rna.tf32.f32 %0, %1;" : "=r"(r) : "f"(f));
    return r;
}
__device__ __forceinline__ float tfr(float f) { return __uint_as_float(f2tf(f)); }
__device__ __forceinline__ void mma_tf32(float c[4],
                                         float a0, float a1, float a2, float a3,
                                         float b0, float b1) {
    asm volatile(
        "mma.sync.aligned.m16n8k8.row.col.f32.tf32.tf32.f32 "
        "{%0,%1,%2,%3}, {%4,%5,%6,%7}, {%8,%9}, {%0,%1,%2,%3};"
        : "+f"(c[0]), "+f"(c[1]), "+f"(c[2]), "+f"(c[3])
        : "r"(__float_as_uint(a0)), "r"(__float_as_uint(a1)),
          "r"(__float_as_uint(a2)), "r"(__float_as_uint(a3)),
          "r"(__float_as_uint(b0)), "r"(__float_as_uint(b1)));
}

// ---------------- kernel 0: weight prep (permute k within 8-blocks + tf32 round) ----------------
__global__ void prep_kernel(const float* __restrict__ qk_w, const float* __restrict__ v_w,
                            const float* __restrict__ w1, const float* __restrict__ w2) {
    int idx = blockIdx.x * 256 + threadIdx.x;     // 0 .. 163839
    if (idx < 32768) {
        int o = idx >> 7, k = idx & 127;
        g_wqk[(o << 7) | perm8(k)] = tfr(qk_w[idx]);
    } else if (idx < 65536) {
        int j = idx - 32768; int o = j >> 7, k = j & 127;
        g_wv[(o << 7) | perm8(k)] = tfr(v_w[j]);
    } else if (idx < 131072) {
        int j = idx - 65536; int o = j >> 8, k = j & 255;
        g_w1p[(o << 8) | perm8(k)] = tfr(w1[j]);
    } else {
        int j = idx - 131072; int o = j >> 8, k = j & 255;
        g_w2p[(o << 8) | perm8(k)] = tfr(w2[j]);
    }
}

// ---------------- kernel 1: continuous relative position bias ----------------
__global__ void cpb_bias_kernel(const float* __restrict__ w1,
                                const float* __restrict__ b1,
                                const float* __restrict__ w2) {
    __shared__ float s_w1[256];
    __shared__ float s_b1[128];
    __shared__ float s_w2[256];
    int tid = threadIdx.x;
    s_w1[tid] = w1[tid];
    if (tid < 128) s_b1[tid] = b1[tid];
    s_w2[tid] = w2[tid];
    __syncthreads();

    int idx = blockIdx.x * 256 + tid;      // < 576*576
    int i = idx / L_, j = idx % L_;
    int yi = i / WID, xi = i % WID;
    int yj = j / WID, xj = j % WID;
    float ry = (float)(yi - yj) * (8.0f / 23.0f);
    float rx = (float)(xi - xj) * (8.0f / 23.0f);
    ry = copysignf(log2f(1.0f + fabsf(ry)) * (1.0f / 3.0f), ry);
    rx = copysignf(log2f(1.0f + fabsf(rx)) * (1.0f / 3.0f), rx);

    float acc0 = 0.f, acc1 = 0.f;
    #pragma unroll 4
    for (int k = 0; k < 128; k++) {
        float h = fmaxf(0.f, ry * s_w1[2 * k] + rx * s_w1[2 * k + 1] + s_b1[k]);
        acc0 += h * s_w2[k];
        acc1 += h * s_w2[128 + k];
    }
    g_bias[idx] = acc0;
    g_bias[L_ * L_ + idx] = acc1;
}

// ---------------- kernel 2: QKV projection, tf32 mma ----------------
// Block: (l-tile 64, bs). 256 threads = 8 warps.
__global__ void qkv_kernel(const float* __restrict__ x) {
    int bs = blockIdx.y;
    int l0 = blockIdx.x * 64;
    extern __shared__ float sm[];
    float* xs   = sm;                   // 128*72
    float* ws   = xs + 128 * 72;        // 64*136
    float* outs = ws + 64 * 136;        // 64*72

    int tid = threadIdx.x;
    const float* xb = x + (size_t)bs * C_ * L_;
    for (int idx = tid; idx < 128 * 16; idx += 256) {
        int c = idx >> 4, lv = idx & 15;
        float4 v4 = *(const float4*)(xb + (size_t)c * L_ + l0 + lv * 4);
        v4.x = tfr(v4.x); v4.y = tfr(v4.y); v4.z = tfr(v4.z); v4.w = tfr(v4.w);
        *(float4*)(xs + c * 72 + lv * 4) = v4;
    }

    int warp = tid >> 5, lane = tid & 31;
    int row = lane >> 2, quad = lane & 3;
    int m0 = (warp & 3) * 16;           // o within chunk
    int n0 = (warp >> 2) * 32;          // l within tile

    for (int ot = 0; ot < 8; ot++) {
        const float* wsrc = (ot < 4) ? g_wqk + (size_t)ot * 64 * C_
                                     : g_wv  + (size_t)(ot - 4) * 64 * C_;
        __syncthreads();
        for (int idx = tid; idx < 64 * 32; idx += 256) {
            int o = idx >> 5, kv = idx & 31;
            *(float4*)(ws + o * 136 + kv * 4) = *(const float4*)(wsrc + (size_t)o * C_ + kv * 4);
        }
        __syncthreads();

        float acc[4][4] = {};
        #pragma unroll
        for (int kk = 0; kk < 16; kk++) {
            int k0 = kk * 8;
            float2 aA = *(float2*)(ws + (m0 + row) * 136 + k0 + 2 * quad);      // a0,a2
            float2 aB = *(float2*)(ws + (m0 + row + 8) * 136 + k0 + 2 * quad);  // a1,a3
            #pragma unroll
            for (int nt = 0; nt < 4; nt++) {
                int n = n0 + nt * 8;
                float b0 = xs[(k0 + quad) * 72 + n + row];
                float b1 = xs[(k0 + quad + 4) * 72 + n + row];
                mma_tf32(acc[nt], aA.x, aB.x, aA.y, aB.y, b0, b1);
            }
        }

        if (ot < 4) {
            // Q/K: outs[l][perm(d)]
            int po0 = perm8(m0 + row), po1 = perm8(m0 + row + 8);
            #pragma unroll
            for (int nt = 0; nt < 4; nt++) {
                int n = n0 + nt * 8 + 2 * quad;
                outs[n * 72 + po0]       = tfr(acc[nt][0]);
                outs[(n + 1) * 72 + po0] = tfr(acc[nt][1]);
                outs[n * 72 + po1]       = tfr(acc[nt][2]);
                outs[(n + 1) * 72 + po1] = tfr(acc[nt][3]);
            }
            __syncthreads();
            float* dst = (ot < 2) ? g_q + (size_t)(bs * 2 + ot) * L_ * QKD_
                                  : g_k + (size_t)(bs * 2 + ot - 2) * L_ * QKD_;
            for (int idx = tid; idx < 64 * 16; idx += 256) {
                int l = idx >> 4, j = idx & 15;
                *(float4*)(dst + (size_t)(l0 + l) * QKD_ + j * 4) =
                    *(float4*)(outs + l * 72 + j * 4);
            }
        } else {
            // V: outs[d][perm(l)]  (transposed, l-interleaved)
            #pragma unroll
            for (int nt = 0; nt < 4; nt++) {
                int cl = n0 + nt * 8 + 2 * quad;
                int p0 = perm8(cl), p1 = perm8(cl + 1);
                outs[(m0 + row) * 72 + p0]     = tfr(acc[nt][0]);
                outs[(m0 + row) * 72 + p1]     = tfr(acc[nt][1]);
                outs[(m0 + row + 8) * 72 + p0] = tfr(acc[nt][2]);
                outs[(m0 + row + 8) * 72 + p1] = tfr(acc[nt][3]);
            }
            __syncthreads();
            int o2 = (ot - 4) * 64;
            int head = o2 >> 7, dof = o2 & 127;
            float* dst = g_v + (size_t)(bs * 2 + head) * VD_ * L_;
            for (int idx = tid; idx < 64 * 16; idx += 256) {
                int o = idx >> 4, j = idx & 15;
                *(float4*)(dst + (size_t)(dof + o) * L_ + l0 + j * 4) =
                    *(float4*)(outs + o * 72 + j * 4);
            }
        }
    }
}

// ---------------- kernel 3: flash attention, tf32 mma, 512 threads, 2 CTAs/SM (R6) ----------------
// smem: qs[64][72], ks[64][72], vt[128][72], ps[64][72], mrow/lrow/arow[64]
__global__ void __launch_bounds__(512, 2) attn_kernel(const float* __restrict__ sa_bias) {
    int qt = blockIdx.x;              // 0..8
    int bh = blockIdx.y;              // 0..127
    int bs = bh >> 1, head = bh & 1;
    int q0 = qt * 64;

    extern __shared__ float sm[];
    float* qs   = sm;                  // 64*72
    float* ks   = qs + 64 * 72;        // 64*72
    float* vt   = ks + 64 * 72;        // 128*72
    float* ps   = vt + 128 * 72;       // 64*72
    float* mrow = ps + 64 * 72;        // 64
    float* lrow = mrow + 64;           // 64
    float* arow = lrow + 64;           // 64

    const float* qg = g_q + (size_t)(bs * 2 + head) * L_ * QKD_;
    const float* kg = g_k + (size_t)(bs * 2 + head) * L_ * QKD_;
    const float* vg = g_v + (size_t)(bs * 2 + head) * VD_ * L_;
    const float* bg = g_bias + (size_t)head * L_ * L_;

    int tid = threadIdx.x;
    int warp = tid >> 5, lane = tid & 31;
    int row = lane >> 2, quad = lane & 3;
    int m0  = (warp & 3) * 16;         // q rows
    int n0s = (warp >> 2) * 16;        // score n-tile (64 cols over 4 warps)
    int n0v = (warp >> 2) * 32;        // AV n-tile (128 d over 4 warps)

    // load q tile [64][64] (d-interleaved, verbatim)
    for (int idx = tid; idx < 64 * 16; idx += 512) {
        int l = idx >> 4, dv = idx & 15;
        *(float4*)(qs + l * 72 + dv * 4) = *(const float4*)(qg + (size_t)(q0 + l) * QKD_ + dv * 4);
    }
    if (tid < 64) { mrow[tid] = -1e30f; lrow[tid] = 0.f; }

    float oac[4][4] = {};

    for (int kt = 0; kt < 9; kt++) {
        __syncthreads();   // previous AV done with vt/ps; qs/mrow init visible on kt=0
        // stage K tile [64 keys][64 d]
        for (int idx = tid; idx < 64 * 16; idx += 512) {
            int l = idx >> 4, dv = idx & 15;
            *(float4*)(ks + l * 72 + dv * 4) =
                *(const float4*)(kg + (size_t)(kt * 64 + l) * QKD_ + dv * 4);
        }
        // stage V tile [128 d][64 keys-interleaved]
        for (int idx = tid; idx < 128 * 16; idx += 512) {
            int d = idx >> 4, j = idx & 15;
            *(float4*)(vt + d * 72 + j * 4) =
                *(const float4*)(vg + (size_t)d * L_ + kt * 64 + j * 4);
        }
        __syncthreads();

        // ---- S = Q K^T (16x16 per warp) + bias, raw into ps (perm cols) ----
        float acc[2][4] = {};
        #pragma unroll
        for (int kk = 0; kk < 8; kk++) {
            int k0 = kk * 8;
            float2 aA = *(float2*)(qs + (m0 + row) * 72 + k0 + 2 * quad);
            float2 aB = *(float2*)(qs + (m0 + row + 8) * 72 + k0 + 2 * quad);
            #pragma unroll
            for (int nt = 0; nt < 2; nt++) {
                float2 bv = *(float2*)(ks + (n0s + nt * 8 + row) * 72 + k0 + 2 * quad);
                mma_tf32(acc[nt], aA.x, aB.x, aA.y, aB.y, bv.x, bv.y);
            }
        }
        {
            int r0 = q0 + m0 + row;
            #pragma unroll
            for (int nt = 0; nt < 2; nt++) {
                int cl = n0s + nt * 8 + 2 * quad;
                int p0 = perm8(cl), p1 = perm8(cl + 1);
                int ct = kt * 64 + cl;
                ps[(m0 + row) * 72 + p0]     = acc[nt][0] * 0.125f + bg[(size_t)r0 * L_ + ct];
                ps[(m0 + row) * 72 + p1]     = acc[nt][1] * 0.125f + bg[(size_t)r0 * L_ + ct + 1];
                ps[(m0 + row + 8) * 72 + p0] = acc[nt][2] * 0.125f + bg[(size_t)(r0 + 8) * L_ + ct];
                ps[(m0 + row + 8) * 72 + p1] = acc[nt][3] * 0.125f + bg[(size_t)(r0 + 8) * L_ + ct + 1];
            }
        }
        __syncthreads();

        // ---- online softmax update: warp owns rows warp*4 .. warp*4+3 ----
        #pragma unroll
        for (int rr = 0; rr < 4; rr++) {
            int r = warp * 4 + rr;
            float2 pv = *(float2*)(ps + r * 72 + 2 * lane);
            float tmax = fmaxf(pv.x, pv.y);
            #pragma unroll
            for (int off = 16; off > 0; off >>= 1)
                tmax = fmaxf(tmax, __shfl_xor_sync(0xffffffffu, tmax, off));
            float mo = mrow[r];
            float mn = fmaxf(mo, tmax);
            float e0 = __expf(pv.x - mn);
            float e1 = __expf(pv.y - mn);
            float2 pr; pr.x = tfr(e0); pr.y = tfr(e1);
            *(float2*)(ps + r * 72 + 2 * lane) = pr;
            float ss = e0 + e1;
            #pragma unroll
            for (int off = 16; off > 0; off >>= 1)
                ss += __shfl_xor_sync(0xffffffffu, ss, off);
            if (lane == 0) {
                float al = __expf(mo - mn);
                arow[r] = al;
                mrow[r] = mn;
                lrow[r] = al * lrow[r] + ss;
            }
        }
        __syncthreads();

        // ---- AV: rescale + accumulate (m16 x n32 per warp) ----
        float al0 = arow[m0 + row], al1 = arow[m0 + row + 8];
        #pragma unroll
        for (int nt = 0; nt < 4; nt++) {
            oac[nt][0] *= al0; oac[nt][1] *= al0;
            oac[nt][2] *= al1; oac[nt][3] *= al1;
        }
        #pragma unroll
        for (int kk = 0; kk < 8; kk++) {
            int kb = kk * 8;
            float2 aA = *(float2*)(ps + (m0 + row) * 72 + kb + 2 * quad);
            float2 aB = *(float2*)(ps + (m0 + row + 8) * 72 + kb + 2 * quad);
            #pragma unroll
            for (int nt = 0; nt < 4; nt++) {
                float2 bv = *(float2*)(vt + (n0v + nt * 8 + row) * 72 + kb + 2 * quad);
                mma_tf32(oac[nt], aA.x, aB.x, aA.y, aB.y, bv.x, bv.y);
            }
        }
    }

    // ---- epilogue: normalize, + sa_bias, ch-interleaved tf32 write ----
    float inv0 = 1.0f / lrow[m0 + row];
    float inv1 = 1.0f / lrow[m0 + row + 8];
    float* og = g_att + (size_t)bs * L_ * HID_;
    int l = q0 + m0 + row;
    #pragma unroll
    for (int nt = 0; nt < 4; nt++) {
        int ch = head * 128 + n0v + nt * 8 + 2 * quad;
        int pc0 = perm8(ch), pc1 = perm8(ch + 1);
        float sb0 = sa_bias[ch], sb1 = sa_bias[ch + 1];
        og[(size_t)l * HID_ + pc0]       = tfr(oac[nt][0] * inv0 + sb0);
        og[(size_t)l * HID_ + pc1]       = tfr(oac[nt][1] * inv0 + sb1);
        og[(size_t)(l + 8) * HID_ + pc0] = tfr(oac[nt][2] * inv1 + sb0);
        og[(size_t)(l + 8) * HID_ + pc1] = tfr(oac[nt][3] * inv1 + sb1);
    }
}

// ---------------- kernel 4: MLP (tf32 mma), l-tile 32, 512 threads, 2 CTAs/SM ----------------
// smem: xsm[32][264], y1s[32][264], wts[256][40]
__global__ void __launch_bounds__(512, 2) mlp_kernel(const float* __restrict__ b1,
                                                     const float* __restrict__ b2,
                                                     float* __restrict__ out) {
    int blk = blockIdx.x;                // 0..1151
    int bs = blk / 18;
    int l0 = (blk % 18) * 32;
    extern __shared__ float sm[];
    float* xsm = sm;                     // 32*264
    float* y1s = xsm + 32 * 264;         // 32*264
    float* wts = y1s + 32 * 264;         // 256*40

    int tid = threadIdx.x;
    int warp = tid >> 5, lane = tid & 31;
    int row = lane >> 2, quad = lane & 3;

    const float* ag = g_att + ((size_t)bs * L_ + l0) * HID_;
    for (int idx = tid; idx < 32 * 64; idx += 512) {
        int p = idx >> 6, iv = idx & 63;
        *(float4*)(xsm + p * 264 + iv * 4) = *(const float4*)(ag + (size_t)p * HID_ + iv * 4);
    }

    // ---- GEMM1: Y1(32x256) = X @ W1^T : warp tile m32 x n16, n0 = warp*16 ----
    int n0 = warp * 16;
    float acc[2][2][4] = {};
    for (int it = 0; it < 8; it++) {
        __syncthreads();
        for (int idx = tid; idx < 256 * 8; idx += 512) {
            int o = idx >> 3, kv = idx & 7;
            *(float4*)(wts + o * 40 + kv * 4) =
                *(const float4*)(g_w1p + (size_t)o * HID_ + it * 32 + kv * 4);
        }
        __syncthreads();
        #pragma unroll
        for (int kk = 0; kk < 4; kk++) {
            int kg = it * 32 + kk * 8;
            int kb = kk * 8;
            float2 aA[2], aB[2];
            #pragma unroll
            for (int mt = 0; mt < 2; mt++) {
                aA[mt] = *(float2*)(xsm + (mt * 16 + row) * 264 + kg + 2 * quad);
                aB[mt] = *(float2*)(xsm + (mt * 16 + row + 8) * 264 + kg + 2 * quad);
            }
            #pragma unroll
            for (int nt = 0; nt < 2; nt++) {
                float2 bv = *(float2*)(wts + (n0 + nt * 8 + row) * 40 + kb + 2 * quad);
                mma_tf32(acc[0][nt], aA[0].x, aB[0].x, aA[0].y, aB[0].y, bv.x, bv.y);
                mma_tf32(acc[1][nt], aA[1].x, aB[1].x, aA[1].y, aB[1].y, bv.x, bv.y);
            }
        }
    }
    // bias + exact GELU -> y1s[p][perm(o)], tf32-rounded
    #pragma unroll
    for (int mt = 0; mt < 2; mt++) {
        #pragma unroll
        for (int nt = 0; nt < 2; nt++) {
            int col = n0 + nt * 8 + 2 * quad;
            int p0 = perm8(col), p1 = perm8(col + 1);
            float bb0 = b1[col], bb1 = b1[col + 1];
            int r = mt * 16 + row;
            float v0 = acc[mt][nt][0] + bb0;
            float v1 = acc[mt][nt][1] + bb1;
            float v2 = acc[mt][nt][2] + bb0;
            float v3 = acc[mt][nt][3] + bb1;
            y1s[r * 264 + p0]       = tfr(0.5f * v0 * (1.0f + erff(v0 * 0.70710678118654752f)));
            y1s[r * 264 + p1]       = tfr(0.5f * v1 * (1.0f + erff(v1 * 0.70710678118654752f)));
            y1s[(r + 8) * 264 + p0] = tfr(0.5f * v2 * (1.0f + erff(v2 * 0.70710678118654752f)));
            y1s[(r + 8) * 264 + p1] = tfr(0.5f * v3 * (1.0f + erff(v3 * 0.70710678118654752f)));
        }
    }
    __syncthreads();

    // ---- GEMM2: OUT(32x128) = Y1 @ W2^T : warp tile m16 x n16 ----
    int m0b = (warp & 1) * 16;
    int n0b = (warp >> 1) * 16;
    float ac2[2][4] = {};
    for (int it = 0; it < 8; it++) {
        for (int idx = tid; idx < 128 * 8; idx += 512) {
            int o = idx >> 3, kv = idx & 7;
            *(float4*)(wts + o * 40 + kv * 4) =
                *(const float4*)(g_w2p + (size_t)o * HID_ + it * 32 + kv * 4);
        }
        __syncthreads();
        #pragma unroll
        for (int kk = 0; kk < 4; kk++) {
            int kg = it * 32 + kk * 8;
            int kb = kk * 8;
            float2 aA = *(float2*)(y1s + (m0b + row) * 264 + kg + 2 * quad);
            float2 aB = *(float2*)(y1s + (m0b + row + 8) * 264 + kg + 2 * quad);
            #pragma unroll
            for (int nt = 0; nt < 2; nt++) {
                float2 bv = *(float2*)(wts + (n0b + nt * 8 + row) * 40 + kb + 2 * quad);
                mma_tf32(ac2[nt], aA.x, aB.x, aA.y, aB.y, bv.x, bv.y);
            }
        }
        __syncthreads();
    }

    // ---- epilogue: + b2, write (bs, o, l) ----
    float* og = out + (size_t)bs * OUTC_ * L_;
    int l = l0 + m0b + row;
    #pragma unroll
    for (int nt = 0; nt < 2; nt++) {
        int col = n0b + nt * 8 + 2 * quad;
        float bb0 = b2[col], bb1 = b2[col + 1];
        og[(size_t)col * L_ + l]           = ac2[nt][0] + bb0;
        og[(size_t)(col + 1) * L_ + l]     = ac2[nt][1] + bb1;
        og[(size_t)col * L_ + l + 8]       = ac2[nt][2] + bb0;
        og[(size_t)(col + 1) * L_ + l + 8] = ac2[nt][3] + bb1;
    }
}

// ---------------- launch ----------------
extern "C" void kernel_launch(void* const* d_in, const int* in_sizes, int n_in,
                              void* d_out, int out_size) {
    const float* x      = (const float*)d_in[0];
    const float* qk_w   = (const float*)d_in[1];
    const float* v_w    = (const float*)d_in[2];
    const float* cpb_w1 = (const float*)d_in[3];
    const float* cpb_b1 = (const float*)d_in[4];
    const float* cpb_w2 = (const float*)d_in[5];
    const float* sa_b   = (const float*)d_in[6];
    const float* mlp_b1 = (const float*)d_in[8];
    const float* mlp_b2 = (const float*)d_in[10];
    float* out = (float*)d_out;

    const int SMEM_QKV = (128 * 72 + 64 * 136 + 64 * 72) * 4;                  // 90112
    const int SMEM_ATT = (64 * 72 * 3 + 128 * 72 + 192) * 4;                   // 92928
    const int SMEM_MLP = (32 * 264 * 2 + 256 * 40) * 4;                        // 108544

    cudaFuncSetAttribute(qkv_kernel,  cudaFuncAttributeMaxDynamicSharedMemorySize, SMEM_QKV);
    cudaFuncSetAttribute(attn_kernel, cudaFuncAttributeMaxDynamicSharedMemorySize, SMEM_ATT);
    cudaFuncSetAttribute(mlp_kernel,  cudaFuncAttributeMaxDynamicSharedMemorySize, SMEM_MLP);

    prep_kernel<<<640, 256>>>(qk_w, v_w, (const float*)d_in[7], (const float*)d_in[9]);
    cpb_bias_kernel<<<(L_ * L_) / 256, 256>>>(cpb_w1, cpb_b1, cpb_w2);
    qkv_kernel<<<dim3(9, BS_), 256, SMEM_QKV>>>(x);
    attn_kernel<<<dim3(9, BS_ * HEADS_), 512, SMEM_ATT>>>(sa_b);
    mlp_kernel<<<BS_ * 18, 512, SMEM_MLP>>>(mlp_b1, mlp_b2, out);
}